// round 15
// baseline (speedup 1.0000x reference)
#include <cuda_runtime.h>
#include <math.h>

#define NB 16
#define NT 32
#define NAq 3
#define NCLS 80
#define CELLS0 196608   // 16*3*64*64
#define CELLS1 49152    // 16*3*32*32
#define CELLS2 12288    // 16*3*16*16
#define TOTAL_CELLS (CELLS0+CELLS1+CELLS2)   // 258048
#define NBLOCKS 504
#define BLK 256
#define NTHREADS (NBLOCKS*BLK)   // 129024 == TOTAL_CELLS/2
#define NTARGWARPS (NB*NT*3)     // 1536

__device__ float g_acc[12];      // cnt[0..2], box[3..5], cls[6..8], obj[9..11]
__device__ unsigned int g_done;

// fast softplus: max(x,0) + log(1 + e^-|x|)  (~1e-7 abs err)
__device__ __forceinline__ float softplusf(float x) {
    return fmaxf(x, 0.0f) + __logf(1.0f + __expf(-fabsf(x)));
}
__device__ __forceinline__ float sigmoidf(float x) {
    return 1.0f / (1.0f + __expf(-x));
}

__device__ __forceinline__ unsigned long long mk_policy() {
    unsigned long long pol;
    asm("createpolicy.fractional.L2::evict_last.b64 %0, 1.0;" : "=l"(pol));
    return pol;
}
__device__ __forceinline__ float ldg_pol(const float* p, unsigned long long pol) {
    float v;
    asm volatile("ld.global.nc.L2::cache_hint.f32 %0, [%1], %2;"
                 : "=f"(v) : "l"(p), "l"(pol));
    return v;
}

// decode linear cell -> address of its objectness logit + scale id
__device__ __forceinline__ const float* obj_addr(
    int idx, const float* __restrict__ inf0, const float* __restrict__ inf1,
    const float* __restrict__ inf2, int& s)
{
    const float* base;
    long local;
    if (idx < CELLS0)               { s = 0; base = inf0; local = idx; }
    else if (idx < CELLS0 + CELLS1) { s = 1; base = inf1; local = idx - CELLS0; }
    else                            { s = 2; base = inf2; local = idx - CELLS0 - CELLS1; }
    return base + local * 85 + 4;
}

__global__ void __launch_bounds__(BLK) yolo_fused(
    const float* __restrict__ inf0, const float* __restrict__ inf1,
    const float* __restrict__ inf2, const float* __restrict__ anchors,
    const float* __restrict__ strides, const float* __restrict__ targets,
    float* __restrict__ out)
{
    const unsigned FULL = 0xFFFFFFFFu;
    int tid  = blockIdx.x * BLK + threadIdx.x;
    int lane = threadIdx.x & 31;
    int gw   = tid >> 5;
    unsigned long long pol = mk_policy();

    // ===== issue BOTH objectness loads up-front, evict_last policy =========
    int sA, sB;
    const float* pA = obj_addr(tid,            inf0, inf1, inf2, sA);
    const float* pB = obj_addr(tid + NTHREADS, inf0, inf1, inf2, sB);
    float vA = ldg_pol(pA, pol);
    float vB = ldg_pol(pB, pol);

    // ===== per-(target,scale) work runs inside the DRAM shadow =============
    if (gw < NTARGWARPS) {
        int t  = gw / 3;
        int ts = gw - t * 3;
        int b  = t >> 5;
        int t_local = t & 31;

        const float* inf = (ts == 0) ? inf0 : (ts == 1) ? inf1 : inf2;
        int   g    = 64 >> ts;
        float rstr = 1.0f / strides[ts];

        // each lane owns one sibling target of the same batch
        int tt = (b << 5) + lane;
        float xl  = targets[tt * 5 + 0];
        float yl  = targets[tt * 5 + 1];
        float wl  = targets[tt * 5 + 2];
        float hl  = targets[tt * 5 + 3];
        float cll = targets[tt * 5 + 4];

        float txl = xl * rstr,   tyl = yl * rstr;
        float cilf = floorf(txl), cjlf = floorf(tyl);
        float fxl = txl - cilf,  fyl = tyl - cjlf;
        float twl = wl * rstr,   thl = hl * rstr;
        int   cil = (int)cilf,   cjl = (int)cjlf;

        // broadcast the warp's own target (lane t_local) to all lanes
        float fx = __shfl_sync(FULL, fxl, t_local);
        float fy = __shfl_sync(FULL, fyl, t_local);
        float tw = __shfl_sync(FULL, twl, t_local);
        float th = __shfl_sync(FULL, thl, t_local);
        int   ci = __shfl_sync(FULL, cil, t_local);
        int   cj = __shfl_sync(FULL, cjl, t_local);
        int   cls = (int)__shfl_sync(FULL, cll, t_local);

        float t_x0 = fx - 0.5f * tw, t_x1 = fx + 0.5f * tw;
        float t_y0 = fy - 0.5f * th, t_y1 = fy + 0.5f * th;
        float t_area = tw * th;

        float l_x0 = fxl - 0.5f * twl, l_x1 = fxl + 0.5f * twl;
        float l_y0 = fyl - 0.5f * thl, l_y1 = fyl + 0.5f * thl;
        float l_area = twl * thl;

        float boxsum = 0.0f, clssum = 0.0f, corr = 0.0f;
        int cnt = 0;

        #pragma unroll
        for (int a = 0; a < NAq; a++) {
            float aw = anchors[(ts * NAq + a) * 2 + 0] * rstr;
            float ah = anchors[(ts * NAq + a) * 2 + 1] * rstr;
            float a_x0 = 0.5f - 0.5f * aw, a_x1 = 0.5f + 0.5f * aw;
            float a_y0 = 0.5f - 0.5f * ah, a_y1 = 0.5f + 0.5f * ah;

            // every lane: IoU of ITS sibling target vs this anchor
            float x0 = fmaxf(l_x0, a_x0), y0 = fmaxf(l_y0, a_y0);
            float x1 = fminf(l_x1, a_x1), y1 = fminf(l_y1, a_y1);
            float inter = (x0 < x1 && y0 < y1) ? (x1 - x0) * (y1 - y0) : 0.0f;
            float iou = inter / (l_area + aw * ah - inter);
            bool  m_l = iou > 0.5f;

            unsigned ball = __ballot_sync(FULL, m_l);
            if ((ball >> t_local) & 1) {            // warp's target matched (uniform)
                cnt++;
                const float* pred = inf + (((long)(b * NAq + a) * g + cj) * g + ci) * 85;

                // ownership: any smaller-index sibling matched at the SAME cell?
                unsigned cellb = __ballot_sync(FULL, m_l && (cil == ci) && (cjl == cj));
                bool owner = (cellb & ((1u << t_local) - 1u)) == 0u;

                if (lane == 0) {
                    float p0 = ldg_pol(pred + 0, pol), p1 = ldg_pol(pred + 1, pol);
                    float p2 = ldg_pol(pred + 2, pol), p3 = ldg_pol(pred + 3, pol);
                    float p4 = ldg_pol(pred + 4, pol);
                    float pxc = sigmoidf(p0), pyc = sigmoidf(p1);
                    float pw = fminf(__expf(p2), 1000.0f) * aw;
                    float ph = fminf(__expf(p3), 1000.0f) * ah;
                    float p_x0 = pxc - 0.5f * pw, p_x1 = pxc + 0.5f * pw;
                    float p_y0 = pyc - 0.5f * ph, p_y1 = pyc + 0.5f * ph;
                    float ix0 = fmaxf(p_x0, t_x0), iy0 = fmaxf(p_y0, t_y0);
                    float ix1 = fminf(p_x1, t_x1), iy1 = fminf(p_y1, t_y1);
                    float pint = (ix0 < ix1 && iy0 < iy1) ? (ix1 - ix0) * (iy1 - iy0) : 0.0f;
                    float uni = pw * ph + t_area - pint;
                    boxsum += 1.0f - pint / uni;
                    if (owner) corr -= p4;          // softplus(-p)-softplus(p) = -p
                }

                // cls BCE across lanes (c = lane, lane+32, lane+64)
                #pragma unroll
                for (int k = 0; k < 3; k++) {
                    int c = lane + k * 32;
                    if (c < NCLS) {
                        float p = ldg_pol(pred + 5 + c, pol);
                        clssum += (c == cls) ? softplusf(-p) : softplusf(p);
                    }
                }
            }
        }

        #pragma unroll
        for (int o = 16; o; o >>= 1)
            clssum += __shfl_xor_sync(FULL, clssum, o);

        if (lane == 0 && cnt > 0) {
            atomicAdd(&g_acc[ts],     (float)cnt);
            atomicAdd(&g_acc[3 + ts], boxsum);
            atomicAdd(&g_acc[6 + ts], clssum);
            atomicAdd(&g_acc[9 + ts], corr);
        }
    }

    // ===== consume objectness loads ========================================
    float spA = softplusf(vA);
    float spB = softplusf(vB);
    float obj0 = ((sA == 0) ? spA : 0.0f) + ((sB == 0) ? spB : 0.0f);
    float obj1 = ((sA == 1) ? spA : 0.0f) + ((sB == 1) ? spB : 0.0f);
    float obj2 = ((sA == 2) ? spA : 0.0f) + ((sB == 2) ? spB : 0.0f);

    // ===== block reduce objectness sums ====================================
    #pragma unroll
    for (int o = 16; o; o >>= 1) {
        obj0 += __shfl_xor_sync(FULL, obj0, o);
        obj1 += __shfl_xor_sync(FULL, obj1, o);
        obj2 += __shfl_xor_sync(FULL, obj2, o);
    }
    __shared__ float sh[3];
    if (threadIdx.x < 3) sh[threadIdx.x] = 0.0f;
    __syncthreads();
    if (lane == 0) {
        if (obj0 != 0.0f) atomicAdd(&sh[0], obj0);
        if (obj1 != 0.0f) atomicAdd(&sh[1], obj1);
        if (obj2 != 0.0f) atomicAdd(&sh[2], obj2);
    }
    __syncthreads();
    if (threadIdx.x < 3 && sh[threadIdx.x] != 0.0f)
        atomicAdd(&g_acc[9 + threadIdx.x], sh[threadIdx.x]);

    // ===== last-block fold + self-reset ====================================
    __threadfence();
    __syncthreads();
    if (threadIdx.x == 0) {
        unsigned d = atomicAdd(&g_done, 1u);
        if (d == gridDim.x - 1) {
            __threadfence();
            volatile float* acc = g_acc;
            const float cells[3] = {(float)CELLS0, (float)CELLS1, (float)CELLS2};
            float box = 0.0f, obj = 0.0f, clsv = 0.0f;
            #pragma unroll
            for (int s = 0; s < 3; s++) {
                float c = fmaxf(acc[s], 1.0f);
                box  += acc[3 + s] / c;
                clsv += acc[6 + s] / (c * (float)NCLS);
                obj  += acc[9 + s] / cells[s];
            }
            out[0] = 3.54f * box + 64.3f * obj + 37.4f * clsv;
            #pragma unroll
            for (int i = 0; i < 12; i++) g_acc[i] = 0.0f;   // reset for replay
            g_done = 0u;
        }
    }
}

// ---------------------------------------------------------------------------
extern "C" void kernel_launch(void* const* d_in, const int* in_sizes, int n_in,
                              void* d_out, int out_size)
{
    const float* inf0    = (const float*)d_in[0];
    const float* inf1    = (const float*)d_in[1];
    const float* inf2    = (const float*)d_in[2];
    const float* anchors = (const float*)d_in[3];
    const float* strides = (const float*)d_in[4];
    const float* targets = (const float*)d_in[5];
    float* out = (float*)d_out;

    yolo_fused<<<NBLOCKS, BLK>>>(inf0, inf1, inf2, anchors, strides, targets, out);
}

// round 17
// speedup vs baseline: 1.1103x; 1.1103x over previous
#include <cuda_runtime.h>
#include <math.h>

#define NB 16
#define NT 32
#define NAq 3
#define NCLS 80
#define CELLS0 196608   // 16*3*64*64
#define CELLS1 49152    // 16*3*32*32
#define CELLS2 12288    // 16*3*16*16
#define TOTAL_CELLS (CELLS0+CELLS1+CELLS2)   // 258048
#define NBLOCKS 504
#define BLK 256
#define NTHREADS (NBLOCKS*BLK)   // 129024 == TOTAL_CELLS/2
#define NTARGWARPS (NB*NT*3)     // 1536

__device__ float g_acc[12];      // cnt[0..2], box[3..5], cls[6..8], obj[9..11]
__device__ unsigned int g_done;

// fast softplus: max(x,0) + log(1 + e^-|x|)  (~1e-7 abs err)
__device__ __forceinline__ float softplusf(float x) {
    return fmaxf(x, 0.0f) + __logf(1.0f + __expf(-fabsf(x)));
}
__device__ __forceinline__ float sigmoidf(float x) {
    return 1.0f / (1.0f + __expf(-x));
}

__device__ __forceinline__ unsigned long long mk_policy() {
    unsigned long long pol;
    asm("createpolicy.fractional.L2::evict_last.b64 %0, 1.0;" : "=l"(pol));
    return pol;
}
__device__ __forceinline__ float ldg_pol(const float* p, unsigned long long pol) {
    float v;
    asm volatile("ld.global.nc.L2::cache_hint.f32 %0, [%1], %2;"
                 : "=f"(v) : "l"(p), "l"(pol));
    return v;
}

// decode linear cell -> address of its objectness logit + scale id
__device__ __forceinline__ const float* obj_addr(
    int idx, const float* __restrict__ inf0, const float* __restrict__ inf1,
    const float* __restrict__ inf2, int& s)
{
    const float* base;
    long local;
    if (idx < CELLS0)               { s = 0; base = inf0; local = idx; }
    else if (idx < CELLS0 + CELLS1) { s = 1; base = inf1; local = idx - CELLS0; }
    else                            { s = 2; base = inf2; local = idx - CELLS0 - CELLS1; }
    return base + local * 85 + 4;
}

__global__ void __launch_bounds__(BLK) yolo_fused(
    const float* __restrict__ inf0, const float* __restrict__ inf1,
    const float* __restrict__ inf2, const float* __restrict__ anchors,
    const float* __restrict__ strides, const float* __restrict__ targets,
    float* __restrict__ out)
{
    const unsigned FULL = 0xFFFFFFFFu;
    int tid  = blockIdx.x * BLK + threadIdx.x;
    int lane = threadIdx.x & 31;
    int gw   = tid >> 5;
    unsigned long long pol = mk_policy();

    // ===== issue BOTH objectness loads up-front, evict_last policy =========
    int sA, sB;
    const float* pA = obj_addr(tid,            inf0, inf1, inf2, sA);
    const float* pB = obj_addr(tid + NTHREADS, inf0, inf1, inf2, sB);
    float vA = ldg_pol(pA, pol);
    float vB = ldg_pol(pB, pol);

    // ===== per-(target,scale) work runs inside the DRAM shadow =============
    if (gw < NTARGWARPS) {
        int t  = gw / 3;
        int ts = gw - t * 3;
        int b  = t >> 5;
        int t_local = t & 31;

        const float* inf = (ts == 0) ? inf0 : (ts == 1) ? inf1 : inf2;
        int   g    = 64 >> ts;
        float rstr = 1.0f / strides[ts];

        // each lane owns one sibling target of the same batch
        int tt = (b << 5) + lane;
        float xl  = targets[tt * 5 + 0];
        float yl  = targets[tt * 5 + 1];
        float wl  = targets[tt * 5 + 2];
        float hl  = targets[tt * 5 + 3];
        float cll = targets[tt * 5 + 4];

        float txl = xl * rstr,   tyl = yl * rstr;
        float cilf = floorf(txl), cjlf = floorf(tyl);
        float fxl = txl - cilf,  fyl = tyl - cjlf;
        float twl = wl * rstr,   thl = hl * rstr;
        int   cil = (int)cilf,   cjl = (int)cjlf;

        // broadcast the warp's own target (lane t_local) to all lanes
        float fx = __shfl_sync(FULL, fxl, t_local);
        float fy = __shfl_sync(FULL, fyl, t_local);
        float tw = __shfl_sync(FULL, twl, t_local);
        float th = __shfl_sync(FULL, thl, t_local);
        int   ci = __shfl_sync(FULL, cil, t_local);
        int   cj = __shfl_sync(FULL, cjl, t_local);
        int   cls = (int)__shfl_sync(FULL, cll, t_local);

        float t_x0 = fx - 0.5f * tw, t_x1 = fx + 0.5f * tw;
        float t_y0 = fy - 0.5f * th, t_y1 = fy + 0.5f * th;
        float t_area = tw * th;

        float l_x0 = fxl - 0.5f * twl, l_x1 = fxl + 0.5f * twl;
        float l_y0 = fyl - 0.5f * thl, l_y1 = fyl + 0.5f * thl;
        float l_area = twl * thl;

        float boxsum = 0.0f, clssum = 0.0f, corr = 0.0f;
        int cnt = 0;

        #pragma unroll
        for (int a = 0; a < NAq; a++) {
            float aw = anchors[(ts * NAq + a) * 2 + 0] * rstr;
            float ah = anchors[(ts * NAq + a) * 2 + 1] * rstr;
            float a_x0 = 0.5f - 0.5f * aw, a_x1 = 0.5f + 0.5f * aw;
            float a_y0 = 0.5f - 0.5f * ah, a_y1 = 0.5f + 0.5f * ah;

            // every lane: IoU of ITS sibling target vs this anchor
            float x0 = fmaxf(l_x0, a_x0), y0 = fmaxf(l_y0, a_y0);
            float x1 = fminf(l_x1, a_x1), y1 = fminf(l_y1, a_y1);
            float inter = (x0 < x1 && y0 < y1) ? (x1 - x0) * (y1 - y0) : 0.0f;
            float iou = inter / (l_area + aw * ah - inter);
            bool  m_l = iou > 0.5f;

            unsigned ball = __ballot_sync(FULL, m_l);
            if ((ball >> t_local) & 1) {            // warp's target matched (uniform)
                cnt++;
                const float* pred = inf + (((long)(b * NAq + a) * g + cj) * g + ci) * 85;

                // ownership: any smaller-index sibling matched at the SAME cell?
                unsigned cellb = __ballot_sync(FULL, m_l && (cil == ci) && (cjl == cj));
                bool owner = (cellb & ((1u << t_local) - 1u)) == 0u;

                if (lane == 0) {
                    float p0 = ldg_pol(pred + 0, pol), p1 = ldg_pol(pred + 1, pol);
                    float p2 = ldg_pol(pred + 2, pol), p3 = ldg_pol(pred + 3, pol);
                    float p4 = ldg_pol(pred + 4, pol);
                    float pxc = sigmoidf(p0), pyc = sigmoidf(p1);
                    float pw = fminf(__expf(p2), 1000.0f) * aw;
                    float ph = fminf(__expf(p3), 1000.0f) * ah;
                    float p_x0 = pxc - 0.5f * pw, p_x1 = pxc + 0.5f * pw;
                    float p_y0 = pyc - 0.5f * ph, p_y1 = pyc + 0.5f * ph;
                    float ix0 = fmaxf(p_x0, t_x0), iy0 = fmaxf(p_y0, t_y0);
                    float ix1 = fminf(p_x1, t_x1), iy1 = fminf(p_y1, t_y1);
                    float pint = (ix0 < ix1 && iy0 < iy1) ? (ix1 - ix0) * (iy1 - iy0) : 0.0f;
                    float uni = pw * ph + t_area - pint;
                    boxsum += 1.0f - pint / uni;
                    if (owner) corr -= p4;          // softplus(-p)-softplus(p) = -p
                }

                // cls BCE across lanes (c = lane, lane+32, lane+64)
                #pragma unroll
                for (int k = 0; k < 3; k++) {
                    int c = lane + k * 32;
                    if (c < NCLS) {
                        float p = ldg_pol(pred + 5 + c, pol);
                        clssum += (c == cls) ? softplusf(-p) : softplusf(p);
                    }
                }
            }
        }

        #pragma unroll
        for (int o = 16; o; o >>= 1)
            clssum += __shfl_xor_sync(FULL, clssum, o);

        if (lane == 0 && cnt > 0) {
            atomicAdd(&g_acc[ts],     (float)cnt);
            atomicAdd(&g_acc[3 + ts], boxsum);
            atomicAdd(&g_acc[6 + ts], clssum);
            atomicAdd(&g_acc[9 + ts], corr);
        }
    }

    // ===== consume objectness loads ========================================
    float spA = softplusf(vA);
    float spB = softplusf(vB);
    float obj0 = ((sA == 0) ? spA : 0.0f) + ((sB == 0) ? spB : 0.0f);
    float obj1 = ((sA == 1) ? spA : 0.0f) + ((sB == 1) ? spB : 0.0f);
    float obj2 = ((sA == 2) ? spA : 0.0f) + ((sB == 2) ? spB : 0.0f);

    // ===== block reduce objectness sums ====================================
    #pragma unroll
    for (int o = 16; o; o >>= 1) {
        obj0 += __shfl_xor_sync(FULL, obj0, o);
        obj1 += __shfl_xor_sync(FULL, obj1, o);
        obj2 += __shfl_xor_sync(FULL, obj2, o);
    }
    __shared__ float sh[3];
    if (threadIdx.x < 3) sh[threadIdx.x] = 0.0f;
    __syncthreads();
    if (lane == 0) {
        if (obj0 != 0.0f) atomicAdd(&sh[0], obj0);
        if (obj1 != 0.0f) atomicAdd(&sh[1], obj1);
        if (obj2 != 0.0f) atomicAdd(&sh[2], obj2);
    }
    __syncthreads();
    if (threadIdx.x < 3 && sh[threadIdx.x] != 0.0f)
        atomicAdd(&g_acc[9 + threadIdx.x], sh[threadIdx.x]);

    // ===== last-block fold + self-reset ====================================
    __threadfence();
    __syncthreads();
    if (threadIdx.x == 0) {
        unsigned d = atomicAdd(&g_done, 1u);
        if (d == gridDim.x - 1) {
            __threadfence();
            volatile float* acc = g_acc;
            const float cells[3] = {(float)CELLS0, (float)CELLS1, (float)CELLS2};
            float box = 0.0f, obj = 0.0f, clsv = 0.0f;
            #pragma unroll
            for (int s = 0; s < 3; s++) {
                float c = fmaxf(acc[s], 1.0f);
                box  += acc[3 + s] / c;
                clsv += acc[6 + s] / (c * (float)NCLS);
                obj  += acc[9 + s] / cells[s];
            }
            out[0] = 3.54f * box + 64.3f * obj + 37.4f * clsv;
            #pragma unroll
            for (int i = 0; i < 12; i++) g_acc[i] = 0.0f;   // reset for replay
            g_done = 0u;
        }
    }
}

// ---------------------------------------------------------------------------
extern "C" void kernel_launch(void* const* d_in, const int* in_sizes, int n_in,
                              void* d_out, int out_size)
{
    const float* inf0    = (const float*)d_in[0];
    const float* inf1    = (const float*)d_in[1];
    const float* inf2    = (const float*)d_in[2];
    const float* anchors = (const float*)d_in[3];
    const float* strides = (const float*)d_in[4];
    const float* targets = (const float*)d_in[5];
    float* out = (float*)d_out;

    yolo_fused<<<NBLOCKS, BLK>>>(inf0, inf1, inf2, anchors, strides, targets, out);
}